// round 11
// baseline (speedup 1.0000x reference)
#include <cuda_runtime.h>
#include <cuda_bf16.h>
#include <math.h>
#include <stdint.h>

#define Dm     256
#define Kc     128
#define NTOK   131072
#define TM     128
#define NTILES (NTOK / TM)        // 1024
#define NTHR   256
#define NWARP  8
#define MAXCTA 160
#define QCAP   2048
#define MARG   0.035f             // >= 2.2x rigorous bf16 error bound 2^-6

// output layout (float32, tuple order flattened+concatenated)
#define OFF_Q    ((size_t)1)
#define OFF_PERP ((size_t)1 + (size_t)NTOK * Dm)
#define OFF_ENC  (OFF_PERP + 1)
#define OFF_IDX  (OFF_ENC + (size_t)NTOK * Kc)

// ---- smem byte offsets ----
#define SROW   528                 // 264 bf16 per row (8 bf16 pad): ldmatrix conflict-free
#define SM_A    0                  // bf16 A  [128][264]  = 67584
#define SM_B    67584              // bf16 B  [128][264]  = 67584
#define SM_E2   135168             // float[128]
#define SM_XN   135680             // float[128]
#define SM_RED  136192             // float[256]
#define SM_SIDX 137216             // int[128]
#define SM_CH   137728             // int[128]
#define SM_RFLG 138240             // int[128]
#define SM_RFUL 138752             // int[128]
#define SM_QB   139264             // ull[128]
#define SM_QL   140288             // int[QCAP] = 8192
#define SM_QCNT 148480
#define SM_TICK 148484
#define SM_ENM  148488
#define SMEM_BYTES 148608

__device__ int   g_hist[MAXCTA * Kc];
__device__ float g_partials[MAXCTA];
__device__ int   g_done = 0;

__device__ __forceinline__ uint32_t smem_u32(const void* p) {
    uint32_t a;
    asm("{ .reg .u64 t; cvta.to.shared.u64 t, %1; cvt.u32.u64 %0, t; }" : "=r"(a) : "l"(p));
    return a;
}
__device__ __forceinline__ uint32_t packbf(float lo, float hi) {
    uint32_t r;
    asm("cvt.rn.bf16x2.f32 %0, %1, %2;" : "=r"(r) : "f"(hi), "f"(lo));
    return r;
}
__device__ __forceinline__ void sts128(uint32_t addr, uint32_t a, uint32_t b, uint32_t c, uint32_t d) {
    asm volatile("st.shared.v4.b32 [%0], {%1,%2,%3,%4};" :: "r"(addr), "r"(a), "r"(b), "r"(c), "r"(d) : "memory");
}
__device__ __forceinline__ void ldsm_x4(uint32_t& r0, uint32_t& r1, uint32_t& r2, uint32_t& r3, uint32_t addr) {
    asm volatile("ldmatrix.sync.aligned.m8n8.x4.shared.b16 {%0,%1,%2,%3}, [%4];"
                 : "=r"(r0), "=r"(r1), "=r"(r2), "=r"(r3) : "r"(addr));
}
__device__ __forceinline__ void mma_bf16(float* d, const uint32_t* a, uint32_t b0, uint32_t b1) {
    asm volatile(
        "mma.sync.aligned.m16n8k16.row.col.f32.bf16.bf16.f32 "
        "{%0,%1,%2,%3}, {%4,%5,%6,%7}, {%8,%9}, {%0,%1,%2,%3};"
        : "+f"(d[0]), "+f"(d[1]), "+f"(d[2]), "+f"(d[3])
        : "r"(a[0]), "r"(a[1]), "r"(a[2]), "r"(a[3]), "r"(b0), "r"(b1));
}
// sortable encoding of float (total order) packed with code: atomicMin picks min dist, then min code
__device__ __forceinline__ unsigned long long packkey(float f, int code) {
    uint32_t b = __float_as_uint(f);
    b = (b & 0x80000000u) ? ~b : (b | 0x80000000u);
    return ((unsigned long long)b << 32) | (unsigned)code;
}

extern __shared__ char smem[];

__global__ void __launch_bounds__(NTHR, 1) vq_kernel(
    const float* __restrict__ inp,
    const float* __restrict__ emb,
    float* __restrict__ out,
    int ncta)
{
    const uint32_t sb = smem_u32(smem);
    float* e2s   = (float*)(smem + SM_E2);
    float* xn    = (float*)(smem + SM_XN);
    float* red   = (float*)(smem + SM_RED);
    int*   sidx  = (int*)(smem + SM_SIDX);
    int*   chist = (int*)(smem + SM_CH);
    int*   rflg  = (int*)(smem + SM_RFLG);
    int*   rful  = (int*)(smem + SM_RFUL);
    unsigned long long* qbest = (unsigned long long*)(smem + SM_QB);
    int*   qlist = (int*)(smem + SM_QL);
    int*   qcnt  = (int*)(smem + SM_QCNT);
    int*   tick  = (int*)(smem + SM_TICK);
    float* enmp  = (float*)(smem + SM_ENM);

    const int tid  = threadIdx.x;
    const int wid  = tid >> 5;
    const int lane = tid & 31;
    const int cta  = blockIdx.x;
    const int wbase = wid * 16;          // this warp's 16 tokens

    if (tid < Kc) chist[tid] = 0;

    // ---- stage B = bf16(emb) [code][d] (pad 264) + e2 fp32 ----
    {
        int code = tid >> 1, half = tid & 1;
        const float* src = emb + code * Dm + half * 128;
        uint32_t dst = sb + SM_B + code * SROW + half * 256;
        float es = 0.f;
        #pragma unroll
        for (int i = 0; i < 16; i++) {
            float4 v0 = *(const float4*)(src + i * 8);
            float4 v1 = *(const float4*)(src + i * 8 + 4);
            es = fmaf(v0.x, v0.x, es); es = fmaf(v0.y, v0.y, es);
            es = fmaf(v0.z, v0.z, es); es = fmaf(v0.w, v0.w, es);
            es = fmaf(v1.x, v1.x, es); es = fmaf(v1.y, v1.y, es);
            es = fmaf(v1.z, v1.z, es); es = fmaf(v1.w, v1.w, es);
            sts128(dst + i * 16,
                   packbf(v0.x, v0.y), packbf(v0.z, v0.w),
                   packbf(v1.x, v1.y), packbf(v1.z, v1.w));
        }
        es += __shfl_xor_sync(0xffffffffu, es, 1);
        if (half == 0) e2s[code] = es;
    }
    __syncthreads();
    if (tid < 32) {      // max ||e|| for margins
        float m = 0.f;
        #pragma unroll
        for (int j = 0; j < 4; j++) m = fmaxf(m, e2s[tid * 4 + j]);
        #pragma unroll
        for (int s = 16; s > 0; s >>= 1) m = fmaxf(m, __shfl_xor_sync(0xffffffffu, m, s));
        if (tid == 0) enmp[0] = sqrtf(m);
    }
    __syncthreads();
    const float enm = enmp[0];

    // per-thread mma addressing (precomputed)
    const uint32_t a_addr0 = sb + SM_A +
        (uint32_t)(wbase + (lane & 7) + ((lane >> 3) & 1) * 8) * SROW + ((lane >> 4) & 1) * 16;
    const uint32_t b_addr0 = sb + SM_B +
        (uint32_t)((lane & 7) + ((lane >> 4) & 1) * 8) * SROW + ((lane >> 3) & 1) * 16;

    float lsum = 0.f;

    // ================= persistent tile loop =================
    for (int tile = cta; tile < NTILES; tile += ncta) {
        const int tb = tile * TM;

        if (tid == 0) qcnt[0] = 0;
        if (tid < TM) { rflg[tid] = 0; rful[tid] = 0; qbest[tid] = ~0ull; }

        // ---- stage A = bf16(inp tile) + ||x|| ----
        {
            int row = tid >> 1, half = tid & 1;
            const float* src = inp + (size_t)(tb + row) * Dm + half * 128;
            uint32_t dst = sb + SM_A + row * SROW + half * 256;
            float xs = 0.f;
            #pragma unroll
            for (int i = 0; i < 16; i++) {
                float4 v0 = *(const float4*)(src + i * 8);
                float4 v1 = *(const float4*)(src + i * 8 + 4);
                xs = fmaf(v0.x, v0.x, xs); xs = fmaf(v0.y, v0.y, xs);
                xs = fmaf(v0.z, v0.z, xs); xs = fmaf(v0.w, v0.w, xs);
                xs = fmaf(v1.x, v1.x, xs); xs = fmaf(v1.y, v1.y, xs);
                xs = fmaf(v1.z, v1.z, xs); xs = fmaf(v1.w, v1.w, xs);
                sts128(dst + i * 16,
                       packbf(v0.x, v0.y), packbf(v0.z, v0.w),
                       packbf(v1.x, v1.y), packbf(v1.z, v1.w));
            }
            xs += __shfl_xor_sync(0xffffffffu, xs, 1);
            if (half == 0) xn[row] = sqrtf(xs);
        }
        __syncthreads();

        // ---- coarse GEMM: dot_bf(x, e); 16 k-slabs x 16 n-tiles ----
        float d[16][4];
        #pragma unroll
        for (int nt = 0; nt < 16; nt++)
            #pragma unroll
            for (int j = 0; j < 4; j++) d[nt][j] = 0.f;

        #pragma unroll 2
        for (int ks = 0; ks < 16; ks++) {
            uint32_t a[4];
            ldsm_x4(a[0], a[1], a[2], a[3], a_addr0 + ks * 32);
            #pragma unroll
            for (int nt2 = 0; nt2 < 8; nt2++) {
                uint32_t b0, b1, b2, b3;
                ldsm_x4(b0, b1, b2, b3, b_addr0 + (uint32_t)(nt2 * 16) * SROW + ks * 32);
                mma_bf16(d[2 * nt2],     a, b0, b1);
                mma_bf16(d[2 * nt2 + 1], a, b2, b3);
            }
        }

        // ---- bound pass: prove argmin or enqueue candidates ----
        {
            const int r0 = wbase + (lane >> 2);
            const int r1 = r0 + 8;
            const float m0 = MARG * xn[r0] * enm;
            const float m1 = MARG * xn[r1] * enm;
            float b0v = 3.4e38f, b1v = 3.4e38f;
            int   b0i = 0, b1i = 0;
            #pragma unroll
            for (int nt = 0; nt < 16; nt++)
                #pragma unroll
                for (int j = 0; j < 2; j++) {
                    int c = nt * 8 + 2 * (lane & 3) + j;
                    float e2c = e2s[c];
                    float s0 = fmaf(-2.f, d[nt][j],     e2c);
                    float s1 = fmaf(-2.f, d[nt][2 + j], e2c);
                    if (s0 < b0v) { b0v = s0; b0i = c; }
                    if (s1 < b1v) { b1v = s1; b1i = c; }
                }
            #pragma unroll
            for (int m = 1; m < 4; m <<= 1) {
                float ov = __shfl_xor_sync(0xffffffffu, b0v, m);
                int   oi = __shfl_xor_sync(0xffffffffu, b0i, m);
                if (ov < b0v || (ov == b0v && oi < b0i)) { b0v = ov; b0i = oi; }
                ov = __shfl_xor_sync(0xffffffffu, b1v, m);
                oi = __shfl_xor_sync(0xffffffffu, b1i, m);
                if (ov < b1v || (ov == b1v && oi < b1i)) { b1v = ov; b1i = oi; }
            }
            const float t0 = b0v + 2.f * m0;
            const float t1 = b1v + 2.f * m1;
            int c0 = 0, c1 = 0;
            #pragma unroll
            for (int nt = 0; nt < 16; nt++)
                #pragma unroll
                for (int j = 0; j < 2; j++) {
                    int c = nt * 8 + 2 * (lane & 3) + j;
                    float e2c = e2s[c];
                    if (fmaf(-2.f, d[nt][j],     e2c) <= t0) c0++;
                    if (fmaf(-2.f, d[nt][2 + j], e2c) <= t1) c1++;
                }
            int tc0 = c0 + __shfl_xor_sync(0xffffffffu, c0, 1);
            tc0 += __shfl_xor_sync(0xffffffffu, tc0, 2);
            int tc1 = c1 + __shfl_xor_sync(0xffffffffu, c1, 1);
            tc1 += __shfl_xor_sync(0xffffffffu, tc1, 2);

            if ((lane & 3) == 0) {
                if (tc0 == 1) sidx[r0] = b0i; else rflg[r0] = 1;
                if (tc1 == 1) sidx[r1] = b1i; else rflg[r1] = 1;
            }
            // enqueue this lane's candidates for ambiguous rows
            if (tc0 > 1 && c0 > 0) {
                int pos = atomicAdd(qcnt, c0);
                if (pos + c0 > QCAP) { rful[r0] = 1; }
                else {
                    #pragma unroll
                    for (int nt = 0; nt < 16; nt++)
                        #pragma unroll
                        for (int j = 0; j < 2; j++) {
                            int c = nt * 8 + 2 * (lane & 3) + j;
                            if (fmaf(-2.f, d[nt][j], e2s[c]) <= t0) qlist[pos++] = (r0 << 8) | c;
                        }
                }
            }
            if (tc1 > 1 && c1 > 0) {
                int pos = atomicAdd(qcnt, c1);
                if (pos + c1 > QCAP) { rful[r1] = 1; }
                else {
                    #pragma unroll
                    for (int nt = 0; nt < 16; nt++)
                        #pragma unroll
                        for (int j = 0; j < 2; j++) {
                            int c = nt * 8 + 2 * (lane & 3) + j;
                            if (fmaf(-2.f, d[nt][2 + j], e2s[c]) <= t1) qlist[pos++] = (r1 << 8) | c;
                        }
                }
            }
        }
        __syncthreads();

        // ---- exact refine: warp per candidate (fp32 dot from gmem, L2-hot) ----
        {
            int nq = qcnt[0]; if (nq > QCAP) nq = QCAP;
            for (int q = wid; q < nq; q += NWARP) {
                int ent = qlist[q];
                int tok = ent >> 8, code = ent & 255;
                const float* xr = inp + (size_t)(tb + tok) * Dm + lane * 8;
                const float* er = emb + (size_t)code * Dm + lane * 8;
                float4 xa = *(const float4*)(xr),  xb2 = *(const float4*)(xr + 4);
                float4 ea = *(const float4*)(er),  eb2 = *(const float4*)(er + 4);
                float dt = xa.x * ea.x;
                dt = fmaf(xa.y, ea.y, dt); dt = fmaf(xa.z, ea.z, dt); dt = fmaf(xa.w, ea.w, dt);
                dt = fmaf(xb2.x, eb2.x, dt); dt = fmaf(xb2.y, eb2.y, dt);
                dt = fmaf(xb2.z, eb2.z, dt); dt = fmaf(xb2.w, eb2.w, dt);
                #pragma unroll
                for (int m = 16; m > 0; m >>= 1) dt += __shfl_xor_sync(0xffffffffu, dt, m);
                if (lane == 0) {
                    float dist = fmaf(-2.f, dt, e2s[code]);
                    atomicMin(&qbest[tok], packkey(dist, code));
                }
            }
            // overflow fallback (expected never): full exact scan, warp per row
            for (int r = wid; r < TM; r += NWARP) if (rful[r]) {
                float bv = 3.4e38f; int bi = 0;
                for (int cc = 0; cc < 4; cc++) {
                    int code = lane + cc * 32;
                    const float* xr = inp + (size_t)(tb + r) * Dm;
                    const float* er = emb + (size_t)code * Dm;
                    float dt = 0.f;
                    for (int i = 0; i < 64; i++) {
                        float4 xv = *(const float4*)(xr + i * 4);
                        float4 ev = *(const float4*)(er + i * 4);
                        dt = fmaf(xv.x, ev.x, dt); dt = fmaf(xv.y, ev.y, dt);
                        dt = fmaf(xv.z, ev.z, dt); dt = fmaf(xv.w, ev.w, dt);
                    }
                    float dist = fmaf(-2.f, dt, e2s[code]);
                    if (dist < bv || (dist == bv && code < bi)) { bv = dist; bi = code; }
                }
                #pragma unroll
                for (int m = 1; m < 32; m <<= 1) {
                    float ov = __shfl_xor_sync(0xffffffffu, bv, m);
                    int   oi = __shfl_xor_sync(0xffffffffu, bi, m);
                    if (ov < bv || (ov == bv && oi < bi)) { bv = ov; bi = oi; }
                }
                if (lane == 0) sidx[r] = bi;
            }
        }
        __syncthreads();

        if (tid < TM) {
            if (rflg[tid] && !rful[tid]) sidx[tid] = (int)(qbest[tid] & 0xFFu);
        }
        __syncthreads();
        if (tid < TM) atomicAdd(&chist[sidx[tid]], 1);

        // ---- quantized + exact loss (region starts at elem 1 -> scalar stores) ----
        float* out_q = out + OFF_Q;
        #pragma unroll 1
        for (int i = tid; i < TM * (Dm / 4); i += NTHR) {   // 32 iters
            int tok = i >> 6, f4 = i & 63;
            int k2 = sidx[tok];
            float4 e = *(const float4*)(emb + (size_t)k2 * Dm + f4 * 4);
            float4 x = *(const float4*)(inp + (size_t)(tb + tok) * Dm + f4 * 4);
            float* qp = out_q + (size_t)(tb + tok) * Dm + f4 * 4;
            qp[0] = e.x; qp[1] = e.y; qp[2] = e.z; qp[3] = e.w;
            float dx = e.x - x.x, dy = e.y - x.y, dz = e.z - x.z, dw = e.w - x.w;
            lsum += dx * dx + dy * dy + dz * dz + dw * dw;
        }

        // ---- one-hot encodings (region start == 2 mod 4 -> float2 ok) ----
        float* out_e = out + OFF_ENC;
        #pragma unroll 1
        for (int i = tid; i < TM * (Kc / 4); i += NTHR) {   // 16 iters
            int tok = i >> 5, f4 = i & 31;
            int k2 = sidx[tok];
            int d0 = f4 * 4;
            float2 v01, v23;
            v01.x = (d0 + 0 == k2) ? 1.f : 0.f;
            v01.y = (d0 + 1 == k2) ? 1.f : 0.f;
            v23.x = (d0 + 2 == k2) ? 1.f : 0.f;
            v23.y = (d0 + 3 == k2) ? 1.f : 0.f;
            float* ep = out_e + (size_t)(tb + tok) * Kc + d0;
            *(float2*)(ep)     = v01;
            *(float2*)(ep + 2) = v23;
        }

        if (tid < TM) out[OFF_IDX + tb + tid] = (float)sidx[tid];
        __syncthreads();   // protect A/sidx/queues before next tile
    }

    // ================= per-CTA results =================
    red[tid] = lsum;
    __syncthreads();
    #pragma unroll
    for (int s = NTHR / 2; s > 0; s >>= 1) {
        if (tid < s) red[tid] += red[tid + s];
        __syncthreads();
    }
    if (tid == 0) g_partials[cta] = red[0];
    if (tid < Kc) g_hist[cta * Kc + tid] = chist[tid];

    __syncthreads();
    __threadfence();
    if (tid == 0) tick[0] = atomicAdd(&g_done, 1);
    __syncthreads();

    // ================= last CTA: loss + perplexity =================
    if (tick[0] == ncta - 1) {
        __threadfence();
        float term = 0.f;
        if (tid < Kc) {
            int cnt = 0;
            for (int b = 0; b < ncta; b++) cnt += g_hist[b * Kc + tid];
            float p = (float)cnt / (float)NTOK;
            term = p * logf(p + 1e-10f);
        }
        red[tid] = term;
        __syncthreads();
        #pragma unroll
        for (int s = NTHR / 2; s > 0; s >>= 1) {
            if (tid < s) red[tid] += red[tid + s];
            __syncthreads();
        }
        float perp = expf(-red[0]);
        __syncthreads();

        red[tid] = (tid < ncta) ? g_partials[tid] : 0.f;
        __syncthreads();
        #pragma unroll
        for (int s = NTHR / 2; s > 0; s >>= 1) {
            if (tid < s) red[tid] += red[tid + s];
            __syncthreads();
        }
        if (tid == 0) {
            out[0]        = 0.25f * red[0] / ((float)NTOK * (float)Dm);
            out[OFF_PERP] = perp;
            g_done = 0;                     // reset for next graph replay
        }
    }
}

// ---------------- launch ----------------
extern "C" void kernel_launch(void* const* d_in, const int* in_sizes, int n_in,
                              void* d_out, int out_size) {
    const float* inp = (const float*)d_in[0];   // [64,2048,256] f32
    const float* emb = (const float*)d_in[1];   // [128,256]     f32
    float* out = (float*)d_out;

    int nsm = 0;
    cudaDeviceGetAttribute(&nsm, cudaDevAttrMultiProcessorCount, 0);
    if (nsm <= 0) nsm = 148;
    if (nsm > MAXCTA) nsm = MAXCTA;
    if (nsm > NTILES) nsm = NTILES;

    cudaFuncSetAttribute(vq_kernel,
                         cudaFuncAttributeMaxDynamicSharedMemorySize, SMEM_BYTES);

    vq_kernel<<<nsm, NTHR, SMEM_BYTES>>>(inp, emb, out, nsm);
}

// round 12
// speedup vs baseline: 1.1833x; 1.1833x over previous
#include <cuda_runtime.h>
#include <cuda_bf16.h>
#include <math.h>
#include <stdint.h>

#define Dm     256
#define Kc     128
#define NTOK   131072
#define TM     128
#define NTILES (NTOK / TM)        // 1024
#define NTHR   512
#define NWARP  16
#define MAXCTA 160
#define QCAP   2048
#define MARG   0.035f             // >= 2.2x rigorous bf16 coarse-dot error bound

// output layout (float32, tuple order flattened+concatenated)
#define OFF_Q    ((size_t)1)
#define OFF_PERP ((size_t)1 + (size_t)NTOK * Dm)
#define OFF_ENC  (OFF_PERP + 1)
#define OFF_IDX  (OFF_ENC + (size_t)NTOK * Kc)

// ---- smem byte offsets ----
#define SROW   528                 // 264 bf16/row: ldmatrix conflict-free (132w, 4r mod 32)
#define SM_A    0                  // bf16 A [128][264] = 67584
#define SM_B    67584              // bf16 B [128][264] = 67584
#define SM_E2   135168             // float[128]
#define SM_XN   135680             // float[128]
#define SM_SIDX 136192             // int[128]
#define SM_CH   136704             // int[128]
#define SM_RFUL 137216             // int[128]
#define SM_QB   137728             // ull[128]
#define SM_RED  138752             // float[512]
#define SM_QL   140800             // int[QCAP]
#define SM_QCNT 148992
#define SM_TICK 148996
#define SM_ENM  149000
#define SMEM_BYTES 149120

__device__ int   g_hist[MAXCTA * Kc];
__device__ float g_partials[MAXCTA];
__device__ int   g_done = 0;

__device__ __forceinline__ uint32_t smem_u32(const void* p) {
    uint32_t a;
    asm("{ .reg .u64 t; cvta.to.shared.u64 t, %1; cvt.u32.u64 %0, t; }" : "=r"(a) : "l"(p));
    return a;
}
__device__ __forceinline__ uint32_t packbf(float lo, float hi) {
    uint32_t r;
    asm("cvt.rn.bf16x2.f32 %0, %1, %2;" : "=r"(r) : "f"(hi), "f"(lo));
    return r;
}
__device__ __forceinline__ void sts64(uint32_t addr, uint32_t a, uint32_t b) {
    asm volatile("st.shared.v2.b32 [%0], {%1,%2};" :: "r"(addr), "r"(a), "r"(b) : "memory");
}
__device__ __forceinline__ void ldsm_x4(uint32_t& r0, uint32_t& r1, uint32_t& r2, uint32_t& r3, uint32_t addr) {
    asm volatile("ldmatrix.sync.aligned.m8n8.x4.shared.b16 {%0,%1,%2,%3}, [%4];"
                 : "=r"(r0), "=r"(r1), "=r"(r2), "=r"(r3) : "r"(addr));
}
__device__ __forceinline__ void mma_bf16(float* d, const uint32_t* a, uint32_t b0, uint32_t b1) {
    asm volatile(
        "mma.sync.aligned.m16n8k16.row.col.f32.bf16.bf16.f32 "
        "{%0,%1,%2,%3}, {%4,%5,%6,%7}, {%8,%9}, {%0,%1,%2,%3};"
        : "+f"(d[0]), "+f"(d[1]), "+f"(d[2]), "+f"(d[3])
        : "r"(a[0]), "r"(a[1]), "r"(a[2]), "r"(a[3]), "r"(b0), "r"(b1));
}
// sortable (dist,code) key: atomicMin => min dist, ties -> min code
__device__ __forceinline__ unsigned long long packkey(float f, int code) {
    uint32_t b = __float_as_uint(f);
    b = (b & 0x80000000u) ? ~b : (b | 0x80000000u);
    return ((unsigned long long)b << 32) | (unsigned)code;
}

extern __shared__ char smem[];

__global__ void __launch_bounds__(NTHR, 1) vq_kernel(
    const float* __restrict__ inp,
    const float* __restrict__ emb,
    float* __restrict__ out,
    int ncta)
{
    const uint32_t sb = smem_u32(smem);
    float* e2s   = (float*)(smem + SM_E2);
    float* xn    = (float*)(smem + SM_XN);
    int*   sidx  = (int*)(smem + SM_SIDX);
    int*   chist = (int*)(smem + SM_CH);
    int*   rful  = (int*)(smem + SM_RFUL);
    unsigned long long* qbest = (unsigned long long*)(smem + SM_QB);
    float* red   = (float*)(smem + SM_RED);
    int*   qlist = (int*)(smem + SM_QL);
    int*   qcnt  = (int*)(smem + SM_QCNT);
    int*   tick  = (int*)(smem + SM_TICK);
    float* enmp  = (float*)(smem + SM_ENM);

    const int tid  = threadIdx.x;
    const int wid  = tid >> 5;
    const int lane = tid & 31;
    const int cta  = blockIdx.x;
    const int wg   = wid >> 1;          // token group: 16 tokens
    const int hh   = wid & 1;           // code half: 64 codes
    const int srow = tid >> 2;          // staging row (4 threads/row)
    const int part = tid & 3;

    if (tid < Kc) chist[tid] = 0;

    // ---- stage B = bf16(emb), 4 threads/row, coalesced; e2 fp32 ----
    {
        const float* src = emb + srow * Dm;
        uint32_t dst = sb + SM_B + srow * SROW;
        float es = 0.f;
        #pragma unroll
        for (int j = 0; j < 16; j++) {
            int c4 = part + 4 * j;
            float4 v = *(const float4*)(src + c4 * 4);
            es = fmaf(v.x, v.x, es); es = fmaf(v.y, v.y, es);
            es = fmaf(v.z, v.z, es); es = fmaf(v.w, v.w, es);
            sts64(dst + c4 * 8, packbf(v.x, v.y), packbf(v.z, v.w));
        }
        es += __shfl_xor_sync(0xffffffffu, es, 1);
        es += __shfl_xor_sync(0xffffffffu, es, 2);
        if (part == 0) e2s[srow] = es;
    }
    __syncthreads();
    if (tid < 32) {      // max ||e||
        float m = 0.f;
        #pragma unroll
        for (int j = 0; j < 4; j++) m = fmaxf(m, e2s[tid * 4 + j]);
        #pragma unroll
        for (int s = 16; s > 0; s >>= 1) m = fmaxf(m, __shfl_xor_sync(0xffffffffu, m, s));
        if (tid == 0) enmp[0] = sqrtf(m);
    }
    __syncthreads();
    const float enm = enmp[0];

    // mma smem addressing
    const uint32_t a_addr0 = sb + SM_A +
        (uint32_t)(wg * 16 + (lane & 7) + ((lane >> 3) & 1) * 8) * SROW + ((lane >> 4) & 1) * 16;
    const uint32_t b_addr0 = sb + SM_B +
        (uint32_t)(hh * 64 + (lane & 7) + ((lane >> 4) & 1) * 8) * SROW + ((lane >> 3) & 1) * 16;

    float lsum = 0.f;

    // ================= persistent tile loop =================
    for (int tile = cta; tile < NTILES; tile += ncta) {
        const int tb = tile * TM;

        if (tid == 0) qcnt[0] = 0;
        if (tid < TM) { rful[tid] = 0; qbest[tid] = ~0ull; }

        // ---- stage A = bf16(inp tile), coalesced, + ||x|| ----
        {
            const float* src = inp + (size_t)(tb + srow) * Dm;
            uint32_t dst = sb + SM_A + srow * SROW;
            float xs = 0.f;
            #pragma unroll
            for (int j = 0; j < 16; j++) {
                int c4 = part + 4 * j;
                float4 v = *(const float4*)(src + c4 * 4);
                xs = fmaf(v.x, v.x, xs); xs = fmaf(v.y, v.y, xs);
                xs = fmaf(v.z, v.z, xs); xs = fmaf(v.w, v.w, xs);
                sts64(dst + c4 * 8, packbf(v.x, v.y), packbf(v.z, v.w));
            }
            xs += __shfl_xor_sync(0xffffffffu, xs, 1);
            xs += __shfl_xor_sync(0xffffffffu, xs, 2);
            if (part == 0) xn[srow] = sqrtf(xs);
        }
        __syncthreads();

        // ---- coarse half-GEMM: 16 tok x 64 codes per warp ----
        float d[8][4];
        #pragma unroll
        for (int nt = 0; nt < 8; nt++)
            #pragma unroll
            for (int j = 0; j < 4; j++) d[nt][j] = 0.f;

        #pragma unroll 4
        for (int ks = 0; ks < 16; ks++) {
            uint32_t a[4];
            ldsm_x4(a[0], a[1], a[2], a[3], a_addr0 + ks * 32);
            #pragma unroll
            for (int nt2 = 0; nt2 < 4; nt2++) {
                uint32_t b0, b1, b2, b3;
                ldsm_x4(b0, b1, b2, b3, b_addr0 + (uint32_t)(nt2 * 16) * SROW + ks * 32);
                mma_bf16(d[2 * nt2],     a, b0, b1);
                mma_bf16(d[2 * nt2 + 1], a, b2, b3);
            }
        }

        // ---- bound pass: per-half threshold, enqueue all within-margin ----
        {
            const int r0 = wg * 16 + (lane >> 2);
            const int r1 = r0 + 8;
            float b0v = 3.4e38f, b1v = 3.4e38f;
            #pragma unroll
            for (int nt = 0; nt < 8; nt++) {
                int cb = hh * 64 + nt * 8 + 2 * (lane & 3);
                float e0 = e2s[cb], e1 = e2s[cb + 1];
                b0v = fminf(b0v, fminf(fmaf(-2.f, d[nt][0], e0), fmaf(-2.f, d[nt][1], e1)));
                b1v = fminf(b1v, fminf(fmaf(-2.f, d[nt][2], e0), fmaf(-2.f, d[nt][3], e1)));
            }
            #pragma unroll
            for (int m = 1; m < 4; m <<= 1) {
                b0v = fminf(b0v, __shfl_xor_sync(0xffffffffu, b0v, m));
                b1v = fminf(b1v, __shfl_xor_sync(0xffffffffu, b1v, m));
            }
            const float t0 = b0v + 2.f * MARG * xn[r0] * enm;
            const float t1 = b1v + 2.f * MARG * xn[r1] * enm;

            int c0 = 0, c1 = 0;
            #pragma unroll
            for (int nt = 0; nt < 8; nt++) {
                int cb = hh * 64 + nt * 8 + 2 * (lane & 3);
                float e0 = e2s[cb], e1 = e2s[cb + 1];
                if (fmaf(-2.f, d[nt][0], e0) <= t0) c0++;
                if (fmaf(-2.f, d[nt][1], e1) <= t0) c0++;
                if (fmaf(-2.f, d[nt][2], e0) <= t1) c1++;
                if (fmaf(-2.f, d[nt][3], e1) <= t1) c1++;
            }
            int tot = c0 + c1;
            if (tot > 0) {
                int pos = atomicAdd(qcnt, tot);
                if (pos + tot > QCAP) {
                    rful[r0] = 1; rful[r1] = 1;
                } else {
                    #pragma unroll
                    for (int nt = 0; nt < 8; nt++) {
                        int cb = hh * 64 + nt * 8 + 2 * (lane & 3);
                        float e0 = e2s[cb], e1 = e2s[cb + 1];
                        if (fmaf(-2.f, d[nt][0], e0) <= t0) qlist[pos++] = (r0 << 8) | cb;
                        if (fmaf(-2.f, d[nt][1], e1) <= t0) qlist[pos++] = (r0 << 8) | (cb + 1);
                        if (fmaf(-2.f, d[nt][2], e0) <= t1) qlist[pos++] = (r1 << 8) | cb;
                        if (fmaf(-2.f, d[nt][3], e1) <= t1) qlist[pos++] = (r1 << 8) | (cb + 1);
                    }
                }
            }
        }
        __syncthreads();

        // ---- exact refine: warp per candidate (fp32, L2-hot) ----
        {
            int nq = qcnt[0]; if (nq > QCAP) nq = QCAP;
            for (int q = wid; q < nq; q += NWARP) {
                int ent = qlist[q];
                int tok = ent >> 8, code = ent & 255;
                const float* xr = inp + (size_t)(tb + tok) * Dm + lane * 8;
                const float* er = emb + (size_t)code * Dm + lane * 8;
                float4 xa = *(const float4*)(xr),  xb2 = *(const float4*)(xr + 4);
                float4 ea = *(const float4*)(er),  eb2 = *(const float4*)(er + 4);
                float dt = xa.x * ea.x;
                dt = fmaf(xa.y, ea.y, dt); dt = fmaf(xa.z, ea.z, dt); dt = fmaf(xa.w, ea.w, dt);
                dt = fmaf(xb2.x, eb2.x, dt); dt = fmaf(xb2.y, eb2.y, dt);
                dt = fmaf(xb2.z, eb2.z, dt); dt = fmaf(xb2.w, eb2.w, dt);
                #pragma unroll
                for (int m = 16; m > 0; m >>= 1) dt += __shfl_xor_sync(0xffffffffu, dt, m);
                if (lane == 0) {
                    float dist = fmaf(-2.f, dt, e2s[code]);
                    atomicMin(&qbest[tok], packkey(dist, code));
                }
            }
            // overflow fallback (expected never): exact full scan
            for (int r = wid; r < TM; r += NWARP) if (rful[r]) {
                float bv = 3.4e38f; int bi = 0;
                for (int cc = 0; cc < 4; cc++) {
                    int code = lane + cc * 32;
                    const float* xr = inp + (size_t)(tb + r) * Dm;
                    const float* er = emb + (size_t)code * Dm;
                    float dt = 0.f;
                    for (int i = 0; i < 64; i++) {
                        float4 xv = *(const float4*)(xr + i * 4);
                        float4 ev = *(const float4*)(er + i * 4);
                        dt = fmaf(xv.x, ev.x, dt); dt = fmaf(xv.y, ev.y, dt);
                        dt = fmaf(xv.z, ev.z, dt); dt = fmaf(xv.w, ev.w, dt);
                    }
                    float dist = fmaf(-2.f, dt, e2s[code]);
                    if (dist < bv || (dist == bv && code < bi)) { bv = dist; bi = code; }
                }
                #pragma unroll
                for (int m = 1; m < 32; m <<= 1) {
                    float ov = __shfl_xor_sync(0xffffffffu, bv, m);
                    int   oi = __shfl_xor_sync(0xffffffffu, bi, m);
                    if (ov < bv || (ov == bv && oi < bi)) { bv = ov; bi = oi; }
                }
                if (lane == 0) sidx[r] = bi;
            }
        }
        __syncthreads();

        if (tid < TM) {
            if (!rful[tid]) sidx[tid] = (int)(qbest[tid] & 0xFFu);
            atomicAdd(&chist[sidx[tid]], 1);
        }
        __syncthreads();

        // ---- quantized + exact loss (region starts at elem 1 -> scalar stores) ----
        float* out_q = out + OFF_Q;
        #pragma unroll 1
        for (int i = tid; i < TM * (Dm / 4); i += NTHR) {   // 16 iters
            int tok = i >> 6, f4 = i & 63;
            int k2 = sidx[tok];
            float4 e = *(const float4*)(emb + (size_t)k2 * Dm + f4 * 4);
            float4 x = *(const float4*)(inp + (size_t)(tb + tok) * Dm + f4 * 4);
            float* qp = out_q + (size_t)(tb + tok) * Dm + f4 * 4;
            qp[0] = e.x; qp[1] = e.y; qp[2] = e.z; qp[3] = e.w;
            float dx = e.x - x.x, dy = e.y - x.y, dz = e.z - x.z, dw = e.w - x.w;
            lsum += dx * dx + dy * dy + dz * dz + dw * dw;
        }

        // ---- one-hot encodings (region start == 2 mod 4 -> float2 ok) ----
        float* out_e = out + OFF_ENC;
        #pragma unroll 1
        for (int i = tid; i < TM * (Kc / 4); i += NTHR) {   // 8 iters
            int tok = i >> 5, f4 = i & 31;
            int k2 = sidx[tok];
            int d0 = f4 * 4;
            float2 v01, v23;
            v01.x = (d0 + 0 == k2) ? 1.f : 0.f;
            v01.y = (d0 + 1 == k2) ? 1.f : 0.f;
            v23.x = (d0 + 2 == k2) ? 1.f : 0.f;
            v23.y = (d0 + 3 == k2) ? 1.f : 0.f;
            float* ep = out_e + (size_t)(tb + tok) * Kc + d0;
            *(float2*)(ep)     = v01;
            *(float2*)(ep + 2) = v23;
        }

        if (tid < TM) out[OFF_IDX + tb + tid] = (float)sidx[tid];
        __syncthreads();   // protect A/sidx/queues before next tile
    }

    // ================= per-CTA results =================
    red[tid] = lsum;
    __syncthreads();
    #pragma unroll
    for (int s = NTHR / 2; s > 0; s >>= 1) {
        if (tid < s) red[tid] += red[tid + s];
        __syncthreads();
    }
    if (tid == 0) g_partials[cta] = red[0];
    if (tid < Kc) g_hist[cta * Kc + tid] = chist[tid];

    __syncthreads();
    __threadfence();
    if (tid == 0) tick[0] = atomicAdd(&g_done, 1);
    __syncthreads();

    // ================= last CTA: loss + perplexity =================
    if (tick[0] == ncta - 1) {
        __threadfence();
        float term = 0.f;
        if (tid < Kc) {
            int cnt = 0;
            for (int b = 0; b < ncta; b++) cnt += g_hist[b * Kc + tid];
            float p = (float)cnt / (float)NTOK;
            term = p * logf(p + 1e-10f);
        }
        red[tid] = term;
        __syncthreads();
        #pragma unroll
        for (int s = NTHR / 2; s > 0; s >>= 1) {
            if (tid < s) red[tid] += red[tid + s];
            __syncthreads();
        }
        float perp = expf(-red[0]);
        __syncthreads();

        red[tid] = (tid < ncta) ? g_partials[tid] : 0.f;
        __syncthreads();
        #pragma unroll
        for (int s = NTHR / 2; s > 0; s >>= 1) {
            if (tid < s) red[tid] += red[tid + s];
            __syncthreads();
        }
        if (tid == 0) {
            out[0]        = 0.25f * red[0] / ((float)NTOK * (float)Dm);
            out[OFF_PERP] = perp;
            g_done = 0;                     // reset for next graph replay
        }
    }
}

// ---------------- launch ----------------
extern "C" void kernel_launch(void* const* d_in, const int* in_sizes, int n_in,
                              void* d_out, int out_size) {
    const float* inp = (const float*)d_in[0];   // [64,2048,256] f32
    const float* emb = (const float*)d_in[1];   // [128,256]     f32
    float* out = (float*)d_out;

    int nsm = 0;
    cudaDeviceGetAttribute(&nsm, cudaDevAttrMultiProcessorCount, 0);
    if (nsm <= 0) nsm = 148;
    if (nsm > MAXCTA) nsm = MAXCTA;
    if (nsm > NTILES) nsm = NTILES;

    cudaFuncSetAttribute(vq_kernel,
                         cudaFuncAttributeMaxDynamicSharedMemorySize, SMEM_BYTES);

    vq_kernel<<<nsm, NTHR, SMEM_BYTES>>>(inp, emb, out, nsm);
}